// round 9
// baseline (speedup 1.0000x reference)
#include <cuda_runtime.h>
#include <cuda_bf16.h>

// CrossHeadOnlineHadamardHook: 32-point Walsh-Hadamard across heads.
// x: (T, 4096) fp32 rows, T = 16384. heads = 32, HEAD_DIM = 128.
//
// R7: smem phase-split to coarsen global read/write interleave.
//   Phase A: CTA streams 4 contiguous token rows (64KB) gmem -> smem
//            as one sequential read burst.
//   Phase B: per-(token, quad) register FWHT from/to smem
//            (LDS.128/STS.128, conflict-free).
//   Phase C: CTA streams 64KB smem -> gmem as one sequential write burst.
// Targets the 21% DRAM-idle cycles (hypothesis: R/W bus turnaround from
// fine-grained global read/write mixing).

#define NUM_HEADS 32
#define HEAD_DIM  128
#define HIDDEN    (NUM_HEADS * HEAD_DIM)        // 4096 floats per token
#define TOKENS_PER_CTA 4
#define THREADS 128
#define F4_PER_TOKEN (HIDDEN / 4)               // 1024 float4
#define F4_PER_CTA (TOKENS_PER_CTA * F4_PER_TOKEN)   // 4096 float4 = 64KB
#define COPY_ITERS (F4_PER_CTA / THREADS)       // 32
#define SMEM_BYTES (F4_PER_CTA * 16)            // 65536

__global__ __launch_bounds__(THREADS)
void had32_crosshead_smem_kernel(const float4* __restrict__ x,
                                 float4* __restrict__ out)
{
    extern __shared__ float4 smem4[];           // 4096 float4 (64KB)

    const size_t cta_base = (size_t)blockIdx.x * F4_PER_CTA;
    const int tid = threadIdx.x;

    // ---- Phase A: contiguous 64KB read burst, gmem -> smem ----
    const float4* __restrict__ gin = x + cta_base;
#pragma unroll
    for (int k = 0; k < COPY_ITERS; ++k) {
        smem4[k * THREADS + tid] = __ldcs(gin + k * THREADS + tid);
    }
    __syncthreads();

    // ---- Phase B: register FWHT per (token, quad) ----
    // warp w (0..3) owns token w; lanes take consecutive quads -> LDS.128
    // across a warp touches 512B of consecutive smem: conflict-free.
    {
        const int tt = tid >> 5;                // token within CTA
        const int q  = tid & 31;                // float4 index within head dim
        float4* __restrict__ tok = smem4 + tt * F4_PER_TOKEN + q;

        float4 v[NUM_HEADS];
#pragma unroll
        for (int h = 0; h < NUM_HEADS; ++h) {
            v[h] = tok[h * (HEAD_DIM / 4)];
        }

#pragma unroll
        for (int s = 1; s < NUM_HEADS; s <<= 1) {
#pragma unroll
            for (int i = 0; i < NUM_HEADS; ++i) {
                if ((i & s) == 0) {
                    float4 a = v[i];
                    float4 b = v[i + s];
                    v[i].x     = a.x + b.x;
                    v[i].y     = a.y + b.y;
                    v[i].z     = a.z + b.z;
                    v[i].w     = a.w + b.w;
                    v[i + s].x = a.x - b.x;
                    v[i + s].y = a.y - b.y;
                    v[i + s].z = a.z - b.z;
                    v[i + s].w = a.w - b.w;
                }
            }
        }

        const float scl = 0.17677669529663687f;  // 1/sqrt(32)
#pragma unroll
        for (int h = 0; h < NUM_HEADS; ++h) {
            float4 r;
            r.x = v[h].x * scl;
            r.y = v[h].y * scl;
            r.z = v[h].z * scl;
            r.w = v[h].w * scl;
            tok[h * (HEAD_DIM / 4)] = r;
        }
    }
    __syncthreads();

    // ---- Phase C: contiguous 64KB write burst, smem -> gmem ----
    float4* __restrict__ gout = out + cta_base;
#pragma unroll
    for (int k = 0; k < COPY_ITERS; ++k) {
        __stcs(gout + k * THREADS + tid, smem4[k * THREADS + tid]);
    }
}

extern "C" void kernel_launch(void* const* d_in, const int* in_sizes, int n_in,
                              void* d_out, int out_size)
{
    const float4* x = (const float4*)d_in[0];
    float4* out = (float4*)d_out;

    // Opt in to >48KB dynamic smem (host-side attribute, not a stream op;
    // idempotent and capture-safe).
    cudaFuncSetAttribute(had32_crosshead_smem_kernel,
                         cudaFuncAttributeMaxDynamicSharedMemorySize,
                         SMEM_BYTES);

    int n = in_sizes[0];                         // total fp32 elements
    int tokens = n / HIDDEN;                     // 16384
    int blocks = tokens / TOKENS_PER_CTA;        // 4096

    had32_crosshead_smem_kernel<<<blocks, THREADS, SMEM_BYTES>>>(x, out);
}

// round 10
// speedup vs baseline: 1.0188x; 1.0188x over previous
#include <cuda_runtime.h>
#include <cuda_bf16.h>

// CrossHeadOnlineHadamardHook: 32-point Walsh-Hadamard across heads.
// x: (T, 4096) fp32 rows, T = 16384. heads = 32, HEAD_DIM = 128.
// For each (t, d): v[h] = x[t*4096 + h*128 + d], v = H32 * v / sqrt(32).
//
// R9: persistent grid-stride version of the R6 float4 kernel.
// One work item = one (token, d-quad): 32 coalesced LDG.128 (512B/warp),
// register FWHT over 4 lanes, 32 coalesced STG.128. Grid is sized to
// exactly fill the chip (148 SMs x 3 CTAs); each thread loops over
// work items, so CTA prologue/epilogue churn (~9 waves previously) is
// eliminated and per-SM outstanding-load depth stays constant end-to-end.

#define NUM_HEADS 32
#define HEAD_DIM  128
#define HIDDEN    (NUM_HEADS * HEAD_DIM)      // 4096
#define QUADS_PER_ROW (HIDDEN / 4)            // 1024 float4 per token row
#define HQUAD_STRIDE (HEAD_DIM / 4)           // 32 float4 between heads
#define THREADS 128
#define NUM_SMS 148
#define CTAS_PER_SM 3

__global__ __launch_bounds__(THREADS)
void had32_crosshead_f4p_kernel(const float4* __restrict__ x,
                                float4* __restrict__ out,
                                int n_items_total)
{
    const int stride = gridDim.x * THREADS;
    const float scl = 0.17677669529663687f;   // 1/sqrt(32)

    for (int item = blockIdx.x * THREADS + threadIdx.x;
         item < n_items_total;
         item += stride)
    {
        int t = item >> 5;          // token index (32 quads per token)
        int q = item & 31;          // which float4 within the head dim

        size_t base = (size_t)t * QUADS_PER_ROW + q;
        const float4* __restrict__ px = x + base;
        float4*       __restrict__ py = out + base;

        float4 v[NUM_HEADS];

        // 32 coalesced LDG.128 (512B/warp), evict-first streaming
#pragma unroll
        for (int h = 0; h < NUM_HEADS; ++h) {
            v[h] = __ldcs(px + (size_t)h * HQUAD_STRIDE);
        }

        // In-register 32-point FWHT over 4 independent lanes
#pragma unroll
        for (int s = 1; s < NUM_HEADS; s <<= 1) {
#pragma unroll
            for (int i = 0; i < NUM_HEADS; ++i) {
                if ((i & s) == 0) {
                    float4 a = v[i];
                    float4 b = v[i + s];
                    v[i].x     = a.x + b.x;
                    v[i].y     = a.y + b.y;
                    v[i].z     = a.z + b.z;
                    v[i].w     = a.w + b.w;
                    v[i + s].x = a.x - b.x;
                    v[i + s].y = a.y - b.y;
                    v[i + s].z = a.z - b.z;
                    v[i + s].w = a.w - b.w;
                }
            }
        }

        // 32 coalesced STG.128, evict-first
#pragma unroll
        for (int h = 0; h < NUM_HEADS; ++h) {
            float4 r;
            r.x = v[h].x * scl;
            r.y = v[h].y * scl;
            r.z = v[h].z * scl;
            r.w = v[h].w * scl;
            __stcs(py + (size_t)h * HQUAD_STRIDE, r);
        }
    }
}

extern "C" void kernel_launch(void* const* d_in, const int* in_sizes, int n_in,
                              void* d_out, int out_size)
{
    const float4* x = (const float4*)d_in[0];
    float4* out = (float4*)d_out;

    int n = in_sizes[0];                 // total fp32 elements (4*4096*4096)
    int n_items = n >> 7;                // one item = 128 floats (quad x 32 heads)

    int blocks = NUM_SMS * CTAS_PER_SM;  // 444 persistent CTAs
    int max_blocks = (n_items + THREADS - 1) / THREADS;
    if (blocks > max_blocks) blocks = max_blocks;

    had32_crosshead_f4p_kernel<<<blocks, THREADS>>>(x, out, n_items);
}

// round 11
// speedup vs baseline: 1.0221x; 1.0032x over previous
#include <cuda_runtime.h>
#include <cuda_bf16.h>

// CrossHeadOnlineHadamardHook: 32-point Walsh-Hadamard across heads.
// x: (T, 4096) fp32 rows, T = 16384. heads = 32, HEAD_DIM = 128.
// For each (t, d): v[h] = x[t*4096 + h*128 + d], v = H32 * v / sqrt(32).
//
// Final form (R6 winner, 256-thread blocks): one thread owns one
// (token, d-quad). 32 coalesced LDG.128 (512B/warp, front-batched for
// max MLP), register FWHT over 4 independent lanes, 32 coalesced
// STG.128. Streaming (.cs) hints on both directions. Measured at
// 6.23 TB/s — the chip's mixed read+write HBM ceiling; smem staging,
// persistence, and cache-policy variants all bench equal or worse.

#define NUM_HEADS 32
#define HEAD_DIM  128
#define HIDDEN    (NUM_HEADS * HEAD_DIM)      // 4096
#define QUADS_PER_ROW (HIDDEN / 4)            // 1024 float4 per token row
#define HQUAD_STRIDE (HEAD_DIM / 4)           // 32 float4 between heads
#define THREADS 256

__global__ __launch_bounds__(THREADS)
void had32_crosshead_f4_kernel(const float4* __restrict__ x,
                               float4* __restrict__ out,
                               int n_items_total)
{
    int item = blockIdx.x * THREADS + threadIdx.x;
    if (item >= n_items_total) return;

    int t = item >> 5;          // token index (32 quads per token)
    int q = item & 31;          // which float4 within the head dim

    size_t base = (size_t)t * QUADS_PER_ROW + q;
    const float4* __restrict__ px = x + base;
    float4*       __restrict__ py = out + base;

    float4 v[NUM_HEADS];

    // 32 coalesced LDG.128 (512B/warp), evict-first streaming
#pragma unroll
    for (int h = 0; h < NUM_HEADS; ++h) {
        v[h] = __ldcs(px + (size_t)h * HQUAD_STRIDE);
    }

    // In-register 32-point FWHT over 4 independent lanes
#pragma unroll
    for (int s = 1; s < NUM_HEADS; s <<= 1) {
#pragma unroll
        for (int i = 0; i < NUM_HEADS; ++i) {
            if ((i & s) == 0) {
                float4 a = v[i];
                float4 b = v[i + s];
                v[i].x     = a.x + b.x;
                v[i].y     = a.y + b.y;
                v[i].z     = a.z + b.z;
                v[i].w     = a.w + b.w;
                v[i + s].x = a.x - b.x;
                v[i + s].y = a.y - b.y;
                v[i + s].z = a.z - b.z;
                v[i + s].w = a.w - b.w;
            }
        }
    }

    const float scl = 0.17677669529663687f;   // 1/sqrt(32)

    // 32 coalesced STG.128, evict-first
#pragma unroll
    for (int h = 0; h < NUM_HEADS; ++h) {
        float4 r;
        r.x = v[h].x * scl;
        r.y = v[h].y * scl;
        r.z = v[h].z * scl;
        r.w = v[h].w * scl;
        __stcs(py + (size_t)h * HQUAD_STRIDE, r);
    }
}

extern "C" void kernel_launch(void* const* d_in, const int* in_sizes, int n_in,
                              void* d_out, int out_size)
{
    const float4* x = (const float4*)d_in[0];
    float4* out = (float4*)d_out;

    int n = in_sizes[0];                 // total fp32 elements (4*4096*4096)
    int n_items = n >> 7;                // one item = quad x 32 heads = 128 floats
    int blocks = (n_items + THREADS - 1) / THREADS;

    had32_crosshead_f4_kernel<<<blocks, THREADS>>>(x, out, n_items);
}

// round 12
// speedup vs baseline: 1.1193x; 1.0951x over previous
#include <cuda_runtime.h>
#include <cuda_bf16.h>

// CrossHeadOnlineHadamardHook: 32-point Walsh-Hadamard across heads.
// x: (T, 4096) fp32 rows, T = 16384. heads = 32, HEAD_DIM = 128.
// For each (t, d): v[h] = x[t*4096 + h*128 + d], v = H32 * v / sqrt(32).
//
// FINAL (= R6 measured best, 82.11us, 6.23 TB/s HBM = chip's mixed R/W
// ceiling). One thread owns one (token, d-quad): 32 front-batched
// coalesced LDG.128 (512B/warp), register FWHT over 4 independent
// lanes, 32 coalesced STG.128, streaming hints both directions.
// 128-thread blocks are load-bearing: 154 regs x 128 thr -> 3 CTAs/SM
// = 12 warps, the minimum that saturates DRAM request depth (256-thr
// blocks drop to 1 CTA/SM / 8 warps and lose ~9% bandwidth).
// Ruled out by measurement: smem phase-split (-12%), persistent grid
// (-10%), wider blocks (-9%), cache-policy and vector-width variants
// (all neutral at the same 6.23 TB/s ceiling).

#define NUM_HEADS 32
#define HEAD_DIM  128
#define HIDDEN    (NUM_HEADS * HEAD_DIM)      // 4096
#define QUADS_PER_ROW (HIDDEN / 4)            // 1024 float4 per token row
#define HQUAD_STRIDE (HEAD_DIM / 4)           // 32 float4 between heads
#define THREADS 128

__global__ __launch_bounds__(THREADS)
void had32_crosshead_f4_kernel(const float4* __restrict__ x,
                               float4* __restrict__ out,
                               int n_items_total)
{
    int item = blockIdx.x * THREADS + threadIdx.x;
    if (item >= n_items_total) return;

    int t = item >> 5;          // token index (32 quads per token)
    int q = item & 31;          // which float4 within the head dim

    size_t base = (size_t)t * QUADS_PER_ROW + q;
    const float4* __restrict__ px = x + base;
    float4*       __restrict__ py = out + base;

    float4 v[NUM_HEADS];

    // 32 coalesced LDG.128 (512B/warp), evict-first streaming
#pragma unroll
    for (int h = 0; h < NUM_HEADS; ++h) {
        v[h] = __ldcs(px + (size_t)h * HQUAD_STRIDE);
    }

    // In-register 32-point FWHT over 4 independent lanes
#pragma unroll
    for (int s = 1; s < NUM_HEADS; s <<= 1) {
#pragma unroll
        for (int i = 0; i < NUM_HEADS; ++i) {
            if ((i & s) == 0) {
                float4 a = v[i];
                float4 b = v[i + s];
                v[i].x     = a.x + b.x;
                v[i].y     = a.y + b.y;
                v[i].z     = a.z + b.z;
                v[i].w     = a.w + b.w;
                v[i + s].x = a.x - b.x;
                v[i + s].y = a.y - b.y;
                v[i + s].z = a.z - b.z;
                v[i + s].w = a.w - b.w;
            }
        }
    }

    const float scl = 0.17677669529663687f;   // 1/sqrt(32)

    // 32 coalesced STG.128, evict-first
#pragma unroll
    for (int h = 0; h < NUM_HEADS; ++h) {
        float4 r;
        r.x = v[h].x * scl;
        r.y = v[h].y * scl;
        r.z = v[h].z * scl;
        r.w = v[h].w * scl;
        __stcs(py + (size_t)h * HQUAD_STRIDE, r);
    }
}

extern "C" void kernel_launch(void* const* d_in, const int* in_sizes, int n_in,
                              void* d_out, int out_size)
{
    const float4* x = (const float4*)d_in[0];
    float4* out = (float4*)d_out;

    int n = in_sizes[0];                 // total fp32 elements (4*4096*4096)
    int n_items = n >> 7;                // one item = quad x 32 heads = 128 floats
    int blocks = (n_items + THREADS - 1) / THREADS;

    had32_crosshead_f4_kernel<<<blocks, THREADS>>>(x, out, n_items);
}